// round 13
// baseline (speedup 1.0000x reference)
#include <cuda_runtime.h>

#define NN 100000
#define NE 1200000
#define NB1 98   // ceil(NN/1024) scan blocks

typedef unsigned long long u64;

// ---- packed f32x2 helpers (sm_103a FFMA2 path; fp32-exact) -----------------
__device__ __forceinline__ u64 pk(float a) {            // {a, a}
    u64 r; asm("mov.b64 %0, {%1, %1};" : "=l"(r) : "f"(a)); return r;
}
__device__ __forceinline__ void fm2(u64& acc, u64 w, u64 m) {   // acc += w*m
    asm("fma.rn.f32x2 %0, %1, %2, %0;" : "+l"(acc) : "l"(w), "l"(m));
}
__device__ __forceinline__ void ad2(u64& acc, u64 v) {          // acc += v
    asm("add.rn.f32x2 %0, %0, %1;" : "+l"(acc) : "l"(v));
}
__device__ __forceinline__ void ml2(u64& acc, u64 v) {          // acc *= v
    asm("mul.rn.f32x2 %0, %0, %1;" : "+l"(acc) : "l"(v));
}
__device__ __forceinline__ float2 up(u64 v) {
    float2 f; asm("mov.b64 {%0, %1}, %2;" : "=f"(f.x), "=f"(f.y) : "l"(v)); return f;
}

// Scratch (device globals — no allocation allowed).
__device__ int    g_is64;           // 1 if edge_index arrives as int64
__device__ int    g_deg[NN];        // in-degree
__device__ int    g_cur[NN];        // scan -> segment start; after fill -> end
__device__ int    g_bsum[128];      // scan block sums
__device__ int    g_esrc[NE];       // CSR: source node per edge slot
__device__ float4 g_h[NN * 16];     // relu(layer1)  [NN,64]
__device__ float4 g_hl[NN * 8];     // h @ W2_l      [NN,32]

// Edge fetch: harness delivers edge_index as int32 (downcast) or raw int64
// (low word at even slot; ids < 100000 so high words are 0).
__device__ __forceinline__ int edge_src(const int* __restrict__ ei, int e) {
    return g_is64 ? __ldg(&ei[2 * e]) : __ldg(&ei[e]);
}
__device__ __forceinline__ int edge_dst(const int* __restrict__ ei, int e) {
    return g_is64 ? __ldg(&ei[2 * NE + 2 * e]) : __ldg(&ei[NE + e]);
}

// ---------------------------------------------------------------------------
// K0: zero degree histogram + dtype sniff
// ---------------------------------------------------------------------------
__global__ void k_zero(const int* __restrict__ ei) {
    int t = blockIdx.x * blockDim.x + threadIdx.x;
    if (t == 0) {
        int o = ei[1] | ei[3] | ei[5] | ei[7];
        g_is64 = (o == 0) ? 1 : 0;
    }
    if (t < NN) g_deg[t] = 0;
}

// ---------------------------------------------------------------------------
// K1: degree histogram
// ---------------------------------------------------------------------------
__global__ void k_deg(const int* __restrict__ ei) {
    int e = blockIdx.x * blockDim.x + threadIdx.x;
    if (e >= NE) return;
    unsigned dst = (unsigned)edge_dst(ei, e);
    if (dst < NN) atomicAdd(&g_deg[dst], 1);
}

// ---------------------------------------------------------------------------
// K2: per-block exclusive scan of g_deg (1024/block, warp-shuffle)
// ---------------------------------------------------------------------------
__global__ void __launch_bounds__(256) k_scan1() {
    __shared__ int ws[8];
    int b = blockIdx.x, t = threadIdx.x;
    int base = b * 1024 + t * 4;
    int v0 = (base + 0 < NN) ? g_deg[base + 0] : 0;
    int v1 = (base + 1 < NN) ? g_deg[base + 1] : 0;
    int v2 = (base + 2 < NN) ? g_deg[base + 2] : 0;
    int v3 = (base + 3 < NN) ? g_deg[base + 3] : 0;
    int tsum = v0 + v1 + v2 + v3;

    int lane = t & 31, w = t >> 5;
    int v = tsum;
#pragma unroll
    for (int off = 1; off < 32; off <<= 1) {
        int y = __shfl_up_sync(0xffffffffu, v, off);
        if (lane >= off) v += y;
    }
    if (lane == 31) ws[w] = v;
    __syncthreads();
    if (t == 0) {
        int a = 0;
#pragma unroll
        for (int i = 0; i < 8; i++) { int x = ws[i]; ws[i] = a; a += x; }
        g_bsum[b] = a;
    }
    __syncthreads();

    int p = (v - tsum) + ws[w];
    if (base + 0 < NN) g_cur[base + 0] = p;
    p += v0;
    if (base + 1 < NN) g_cur[base + 1] = p;
    p += v1;
    if (base + 2 < NN) g_cur[base + 2] = p;
    p += v2;
    if (base + 3 < NN) g_cur[base + 3] = p;
}

// K2b: exclusive scan of the 98 block sums
__global__ void __launch_bounds__(128) k_scan2() {
    __shared__ int s[128];
    int t = threadIdx.x;
    int own = (t < NB1) ? g_bsum[t] : 0;
    s[t] = own;
    __syncthreads();
#pragma unroll
    for (int off = 1; off < 128; off <<= 1) {
        int x = (t >= off) ? s[t - off] : 0;
        __syncthreads();
        s[t] += x;
        __syncthreads();
    }
    if (t < NB1) g_bsum[t] = s[t] - own;
}

// K2c: add block offsets
__global__ void k_scan3() {
    int i = blockIdx.x * blockDim.x + threadIdx.x;
    if (i < NN) g_cur[i] += g_bsum[i >> 10];
}

// ---------------------------------------------------------------------------
// K3: fill CSR edge array. After this, g_cur[n] == segment END for node n.
// ---------------------------------------------------------------------------
__global__ void k_fill(const int* __restrict__ ei) {
    int e = blockIdx.x * blockDim.x + threadIdx.x;
    if (e >= NE) return;
    unsigned src = (unsigned)edge_src(ei, e);
    unsigned dst = (unsigned)edge_dst(ei, e);
    if (src >= NN || dst >= NN) return;
    int pos = atomicAdd(&g_cur[dst], 1);
    if ((unsigned)pos < NE) g_esrc[pos] = (int)src;
}

// ---------------------------------------------------------------------------
// K4: fused layer 1 + hl, dense math in packed f32x2.
// Phase A: gather-mean of x (32 nodes x 16 chunks, f32x2 adds).
// Phase B: h = relu(agg @ W1_l + x @ W1_r + b1)  (FFMA2)
// Phase C: hl = h @ W2_l (k-split across lane halves + shfl combine, FFMA2)
// Static smem 48KB: sWl 16K + sWr 16K + sW2l 8K + sAgg 8K. NN % 32 == 0.
// ---------------------------------------------------------------------------
__global__ void __launch_bounds__(512) k_layer1(const float4* __restrict__ x4,
                                                const float4* __restrict__ Wl,
                                                const float4* __restrict__ Wr,
                                                const float4* __restrict__ W2l,
                                                const float4* __restrict__ b1) {
    __shared__ float4 sWl[1024];
    __shared__ float4 sWr[1024];
    __shared__ float4 sW2l[512];
    __shared__ float4 sAgg[32 * 16];
    int tid = threadIdx.x;
    for (int i = tid; i < 1024; i += 512) { sWl[i] = Wl[i]; sWr[i] = Wr[i]; }
    sW2l[tid] = W2l[tid];

    int slot = tid >> 4;           // 0..31
    int c    = tid & 15;           // channel chunk / output j4
    int n    = blockIdx.x * 32 + slot;

    // --- Phase A: gather (f32x2 accumulate) ---
    const ulonglong2* x2 = (const ulonglong2*)x4;
    int end = g_cur[n];
    int d   = g_deg[n];
    int j   = end - d;
    ulonglong2 A0 = make_ulonglong2(0ull, 0ull);
    ulonglong2 A1 = make_ulonglong2(0ull, 0ull);
    for (; j + 4 <= end; j += 4) {
        int i0 = __ldg(&g_esrc[j + 0]);
        int i1 = __ldg(&g_esrc[j + 1]);
        int i2 = __ldg(&g_esrc[j + 2]);
        int i3 = __ldg(&g_esrc[j + 3]);
        ulonglong2 v0 = __ldg(&x2[i0 * 16 + c]);
        ulonglong2 v1 = __ldg(&x2[i1 * 16 + c]);
        ulonglong2 v2 = __ldg(&x2[i2 * 16 + c]);
        ulonglong2 v3 = __ldg(&x2[i3 * 16 + c]);
        ad2(A0.x, v0.x); ad2(A0.y, v0.y);
        ad2(A1.x, v1.x); ad2(A1.y, v1.y);
        ad2(A0.x, v2.x); ad2(A0.y, v2.y);
        ad2(A1.x, v3.x); ad2(A1.y, v3.y);
    }
    for (; j < end; j++) {
        int s = __ldg(&g_esrc[j]);
        ulonglong2 v = __ldg(&x2[s * 16 + c]);
        ad2(A0.x, v.x); ad2(A0.y, v.y);
    }
    ad2(A0.x, A1.x); ad2(A0.y, A1.y);
    u64 iv = pk(1.0f / fmaxf((float)d, 1.0f));
    ml2(A0.x, iv); ml2(A0.y, iv);
    {
        float2 p0 = up(A0.x), p1 = up(A0.y);
        sAgg[slot * 16 + c] = make_float4(p0.x, p0.y, p1.x, p1.y);
    }
    __syncthreads();

    // --- Phase B: dense (FFMA2) ---
    int j4 = c;
    const ulonglong2* Wl2 = (const ulonglong2*)sWl;
    const ulonglong2* Wr2 = (const ulonglong2*)sWr;
    u64 lxy = 0, lzw = 0, rxy = 0, rzw = 0;
#pragma unroll 4
    for (int k4 = 0; k4 < 16; k4++) {
        float4 a  = sAgg[slot * 16 + k4];
        float4 xv = __ldg(&x4[n * 16 + k4]);
        u64 ma0 = pk(a.x),  ma1 = pk(a.y),  ma2 = pk(a.z),  ma3 = pk(a.w);
        u64 mx0 = pk(xv.x), mx1 = pk(xv.y), mx2 = pk(xv.z), mx3 = pk(xv.w);
        ulonglong2 w;
        w = Wl2[(k4 * 4 + 0) * 16 + j4]; fm2(lxy, w.x, ma0); fm2(lzw, w.y, ma0);
        w = Wl2[(k4 * 4 + 1) * 16 + j4]; fm2(lxy, w.x, ma1); fm2(lzw, w.y, ma1);
        w = Wl2[(k4 * 4 + 2) * 16 + j4]; fm2(lxy, w.x, ma2); fm2(lzw, w.y, ma2);
        w = Wl2[(k4 * 4 + 3) * 16 + j4]; fm2(lxy, w.x, ma3); fm2(lzw, w.y, ma3);
        w = Wr2[(k4 * 4 + 0) * 16 + j4]; fm2(rxy, w.x, mx0); fm2(rzw, w.y, mx0);
        w = Wr2[(k4 * 4 + 1) * 16 + j4]; fm2(rxy, w.x, mx1); fm2(rzw, w.y, mx1);
        w = Wr2[(k4 * 4 + 2) * 16 + j4]; fm2(rxy, w.x, mx2); fm2(rzw, w.y, mx2);
        w = Wr2[(k4 * 4 + 3) * 16 + j4]; fm2(rxy, w.x, mx3); fm2(rzw, w.y, mx3);
    }
    float4 bb = __ldg(&b1[j4]);
    float2 l0 = up(lxy), l1 = up(lzw), r0 = up(rxy), r1 = up(rzw);
    float4 r;
    r.x = fmaxf(l0.x + r0.x + bb.x, 0.f);
    r.y = fmaxf(l0.y + r0.y + bb.y, 0.f);
    r.z = fmaxf(l1.x + r1.x + bb.z, 0.f);
    r.w = fmaxf(l1.y + r1.y + bb.w, 0.f);
    g_h[n * 16 + j4] = r;

    // --- Phase C: fused hl = h @ W2_l (FFMA2) ---
    __syncwarp();                       // all lanes done reading sAgg (agg)
    sAgg[slot * 16 + j4] = r;           // row now holds h for this node
    __syncwarp();

    int jo = c & 7;                     // output float4 col 0..7
    int kh = (c >> 3) * 8;              // k4 half: 0 or 8
    const ulonglong2* W2l2 = (const ulonglong2*)sW2l;
    u64 pxy = 0, pzw = 0;
#pragma unroll
    for (int kk = 0; kk < 8; kk++) {
        float4 h = sAgg[slot * 16 + kh + kk];
        u64 m0 = pk(h.x), m1 = pk(h.y), m2 = pk(h.z), m3 = pk(h.w);
        int kr = (kh + kk) * 4;
        ulonglong2 w;
        w = W2l2[(kr + 0) * 8 + jo]; fm2(pxy, w.x, m0); fm2(pzw, w.y, m0);
        w = W2l2[(kr + 1) * 8 + jo]; fm2(pxy, w.x, m1); fm2(pzw, w.y, m1);
        w = W2l2[(kr + 2) * 8 + jo]; fm2(pxy, w.x, m2); fm2(pzw, w.y, m2);
        w = W2l2[(kr + 3) * 8 + jo]; fm2(pxy, w.x, m3); fm2(pzw, w.y, m3);
    }
    // combine the two k-halves: lane c (+) lane c+8 within each 16-group
    {
        u64 oxy = __shfl_down_sync(0xffffffffu, pxy, 8, 16);
        u64 ozw = __shfl_down_sync(0xffffffffu, pzw, 8, 16);
        ad2(pxy, oxy); ad2(pzw, ozw);
    }
    if (c < 8) {
        float2 p0 = up(pxy), p1 = up(pzw);
        g_hl[n * 8 + jo] = make_float4(p0.x, p0.y, p1.x, p1.y);
    }
}

// ---------------------------------------------------------------------------
// K6: fused layer 2: out = mean-agg(hl) + h @ W2_r + b2   (FFMA2 dense)
// ---------------------------------------------------------------------------
__global__ void __launch_bounds__(512) k_layer2(const float4* __restrict__ W2r,
                                                const float4* __restrict__ b2,
                                                float4* __restrict__ out4) {
    __shared__ float4 sW[512];
    __shared__ float4 sAgg[64 * 8];
    int tid = threadIdx.x;
    sW[tid] = W2r[tid];

    int slot = tid >> 3;          // 0..63
    int c    = tid & 7;
    int n    = blockIdx.x * 64 + slot;

    const ulonglong2* hl2 = (const ulonglong2*)g_hl;
    ulonglong2 A0 = make_ulonglong2(0ull, 0ull);
    ulonglong2 A1 = make_ulonglong2(0ull, 0ull);
    if (n < NN) {
        int end = g_cur[n];
        int d   = g_deg[n];
        int j   = end - d;
        for (; j + 4 <= end; j += 4) {
            int i0 = __ldg(&g_esrc[j + 0]);
            int i1 = __ldg(&g_esrc[j + 1]);
            int i2 = __ldg(&g_esrc[j + 2]);
            int i3 = __ldg(&g_esrc[j + 3]);
            ulonglong2 v0 = __ldg(&hl2[i0 * 8 + c]);
            ulonglong2 v1 = __ldg(&hl2[i1 * 8 + c]);
            ulonglong2 v2 = __ldg(&hl2[i2 * 8 + c]);
            ulonglong2 v3 = __ldg(&hl2[i3 * 8 + c]);
            ad2(A0.x, v0.x); ad2(A0.y, v0.y);
            ad2(A1.x, v1.x); ad2(A1.y, v1.y);
            ad2(A0.x, v2.x); ad2(A0.y, v2.y);
            ad2(A1.x, v3.x); ad2(A1.y, v3.y);
        }
        for (; j < end; j++) {
            int s = __ldg(&g_esrc[j]);
            ulonglong2 v = __ldg(&hl2[s * 8 + c]);
            ad2(A0.x, v.x); ad2(A0.y, v.y);
        }
        ad2(A0.x, A1.x); ad2(A0.y, A1.y);
        u64 iv = pk(1.0f / fmaxf((float)d, 1.0f));
        ml2(A0.x, iv); ml2(A0.y, iv);
    }
    {
        float2 p0 = up(A0.x), p1 = up(A0.y);
        sAgg[slot * 8 + c] = make_float4(p0.x, p0.y, p1.x, p1.y);
    }
    __syncthreads();

    int j4 = c;
    if (n >= NN) return;
    const ulonglong2* W2 = (const ulonglong2*)sW;
    u64 axy = 0, azw = 0;
#pragma unroll 4
    for (int k4 = 0; k4 < 16; k4++) {
        float4 h = g_h[n * 16 + k4];
        u64 m0 = pk(h.x), m1 = pk(h.y), m2 = pk(h.z), m3 = pk(h.w);
        ulonglong2 w;
        w = W2[(k4 * 4 + 0) * 8 + j4]; fm2(axy, w.x, m0); fm2(azw, w.y, m0);
        w = W2[(k4 * 4 + 1) * 8 + j4]; fm2(axy, w.x, m1); fm2(azw, w.y, m1);
        w = W2[(k4 * 4 + 2) * 8 + j4]; fm2(axy, w.x, m2); fm2(azw, w.y, m2);
        w = W2[(k4 * 4 + 3) * 8 + j4]; fm2(axy, w.x, m3); fm2(azw, w.y, m3);
    }
    float2 a0 = up(axy), a1 = up(azw);
    float4 ag = sAgg[slot * 8 + j4];
    float4 bb = __ldg(&b2[j4]);
    float4 r;
    r.x = a0.x + ag.x + bb.x;
    r.y = a0.y + ag.y + bb.y;
    r.z = a1.x + ag.z + bb.z;
    r.w = a1.y + ag.w + bb.w;
    out4[n * 8 + j4] = r;
}

// ---------------------------------------------------------------------------
// Launch. Inputs identified BY SIZE (robust to metadata ordering):
//   x: 6,400,000   edge_index: 2,400,000   W1_l/W1_r: 4,096 (l first)
//   b1: 64         W2_l/W2_r: 2,048 (l first)   b2: 32
// output: [100000,32] f32
// ---------------------------------------------------------------------------
extern "C" void kernel_launch(void* const* d_in, const int* in_sizes, int n_in,
                              void* d_out, int out_size) {
    const float4* x4  = 0;
    const int*    ei  = 0;
    const float4* W1l = 0, *W1r = 0, *b1 = 0;
    const float4* W2l = 0, *W2r = 0, *b2 = 0;

    for (int i = 0; i < n_in; i++) {
        switch (in_sizes[i]) {
            case 6400000: x4 = (const float4*)d_in[i]; break;
            case 2400000: ei = (const int*)d_in[i]; break;
            case 4096:    if (!W1l) W1l = (const float4*)d_in[i];
                          else      W1r = (const float4*)d_in[i]; break;
            case 64:      b1 = (const float4*)d_in[i]; break;
            case 2048:    if (!W2l) W2l = (const float4*)d_in[i];
                          else      W2r = (const float4*)d_in[i]; break;
            case 32:      b2 = (const float4*)d_in[i]; break;
            default: break;
        }
    }
    if (!x4 || !ei || !W1l || !W1r || !b1 || !W2l || !W2r || !b2) return;

    float4* out4 = (float4*)d_out;

    k_zero<<<(NN + 255) / 256, 256>>>(ei);
    k_deg<<<(NE + 255) / 256, 256>>>(ei);
    k_scan1<<<NB1, 256>>>();
    k_scan2<<<1, 128>>>();
    k_scan3<<<(NN + 255) / 256, 256>>>();
    k_fill<<<(NE + 255) / 256, 256>>>(ei);
    k_layer1<<<NN / 32, 512>>>(x4, W1l, W1r, W2l, b1);
    k_layer2<<<(NN + 63) / 64, 512>>>(W2r, b2, out4);
}